// round 1
// baseline (speedup 1.0000x reference)
#include <cuda_runtime.h>

// Problem dims (fixed by the dataset)
constexpr int Bn = 16, Tn = 4096, In = 32, On = 32;

// Chunked-scan parameters
constexpr int C  = 16;            // time chunks
constexpr int L  = Tn / C;        // 256 outputs per chunk
constexpr int W  = 96;            // warm-up steps (pole^96 <= ~4e-11)
constexpr int TS = 16;            // time sub-tile
constexpr int WARMSUB = W / TS;   // 6
constexpr int NSUB = (W + L) / TS; // 22
constexpr int BP = Bn / 2;        // batch pairs (f32x2 packing)

using u64 = unsigned long long;

// ---- packed f32x2 helpers (sm_103a) ----
__device__ __forceinline__ u64 pack2(float lo, float hi) {
    u64 r; asm("mov.b64 %0, {%1, %2};" : "=l"(r) : "f"(lo), "f"(hi)); return r;
}
__device__ __forceinline__ float2 unpack2(u64 v) {
    float2 r; asm("mov.b64 {%0, %1}, %2;" : "=f"(r.x), "=f"(r.y) : "l"(v)); return r;
}
__device__ __forceinline__ u64 fma2(u64 a, u64 b, u64 c) {
    u64 d; asm("fma.rn.f32x2 %0, %1, %2, %3;" : "=l"(d) : "l"(a), "l"(b), "l"(c)); return d;
}
__device__ __forceinline__ u64 mul2(u64 a, u64 b) {
    u64 d; asm("mul.rn.f32x2 %0, %1, %2;" : "=l"(d) : "l"(a), "l"(b)); return d;
}
__device__ __forceinline__ u64 add2(u64 a, u64 b) {
    u64 d; asm("add.rn.f32x2 %0, %1, %2;" : "=l"(d) : "l"(a), "l"(b)); return d;
}

// SMEM layout (u64 units): ubuf[2][TS*In], ybuf[On][TS*33], outb[2][TS*33]
constexpr int UBUF_E = TS * In;      // 512
constexpr int YROW   = 33;           // +1 pad -> conflict-free transpose
constexpr int YBUF_W = TS * YROW;    // 528
constexpr int SMEM_U64 = 2 * UBUF_E + On * YBUF_W + 2 * YBUF_W;
constexpr int SMEM_BYTES = SMEM_U64 * 8;   // 151,808 B

__global__ void __launch_bounds__(1024, 1)
mimo_iir_kernel(const float* __restrict__ u_in,
                const float* __restrict__ b_co,
                const float* __restrict__ a_co,
                float* __restrict__ y_out)
{
    extern __shared__ u64 sm[];
    u64* ubuf = sm;                        // double-buffered u tile (packed b0,b1)
    u64* ybuf = sm + 2 * UBUF_E;           // per-warp [TS][33] transpose buffer
    u64* outb = ybuf + On * YBUF_W;        // double-buffered output tile [TS][33]

    const int c    = blockIdx.x;           // chunk
    const int bp   = blockIdx.y;           // batch pair
    const int tid  = threadIdx.x;
    const int wid  = tid >> 5;             // o channel
    const int lane = tid & 31;             // i channel

    // per-(o,i) coefficients, broadcast into both packed halves
    const int oi = wid * In + lane;
    const float b0f = b_co[oi * 3 + 0], b1f = b_co[oi * 3 + 1], b2f = b_co[oi * 3 + 2];
    const float a1f = a_co[oi * 2 + 0], a2f = a_co[oi * 2 + 1];
    const u64 B0 = pack2(b0f, b0f), B1 = pack2(b1f, b1f), B2 = pack2(b2f, b2f);
    const u64 A1 = pack2(-a1f, -a1f), A2 = pack2(-a2f, -a2f);

    const int t0 = c * L - W;              // first (warm-up) step; <0 only for c==0 -> zero pad (exact)
    const float* U0 = u_in + (size_t)(bp * 2)     * Tn * In;
    const float* U1 = u_in + (size_t)(bp * 2 + 1) * Tn * In;
    float* Y0 = y_out + (size_t)(bp * 2)     * Tn * On;
    float* Y1 = y_out + (size_t)(bp * 2 + 1) * Tn * On;

    u64* myy = ybuf + wid * YBUF_W;

    const bool loader = tid < UBUF_E;      // first 512 threads stage u
    const int ltl = tid >> 5;              // 0..15 (time row)
    const int li  = tid & 31;              // i

    // preload sub-tile 0
    if (loader) {
        int t = t0 + ltl;
        float v0 = 0.f, v1 = 0.f;
        if (t >= 0) { v0 = U0[t * In + li]; v1 = U1[t * In + li]; }
        ubuf[ltl * In + li] = pack2(v0, v1);
    }
    __syncthreads();

    // rolling recursion state (packed over 2 batches); zero-init = warm-up premise
    u64 u1 = 0ull, u2 = 0ull, y1 = 0ull, y2 = 0ull;

    for (int s = 0; s < NSUB; ++s) {
        const u64* ub = ubuf + (s & 1) * UBUF_E;

        // prefetch next u sub-tile into registers (LDG overlaps compute)
        float p0 = 0.f, p1 = 0.f;
        if (loader && (s + 1) < NSUB) {
            int t = t0 + (s + 1) * TS + ltl;
            if (t >= 0) { p0 = U0[t * In + li]; p1 = U1[t * In + li]; }
        }

        if (s < WARMSUB) {
            // warm-up: recursion only, no output
            #pragma unroll
            for (int k = 0; k < TS; ++k) {
                u64 u0 = ub[k * In + lane];
                u64 x = fma2(B0, u0, fma2(B1, u1, mul2(B2, u2)));
                u64 y = fma2(A1, y1, fma2(A2, y2, x));
                u2 = u1; u1 = u0; y2 = y1; y1 = y;
            }
        } else {
            #pragma unroll
            for (int k = 0; k < TS; ++k) {
                u64 u0 = ub[k * In + lane];
                u64 x = fma2(B0, u0, fma2(B1, u1, mul2(B2, u2)));
                u64 y = fma2(A1, y1, fma2(A2, y2, x));
                myy[k * YROW + lane] = y;     // [t][i], conflict-free
                u2 = u1; u1 = u0; y2 = y1; y1 = y;
            }
            __syncwarp();
            // transpose-reduce over i: lane -> (t = lane&15, half = lane>>4 sums 16 i's)
            {
                const int tl = lane & 15, half = lane >> 4;
                const u64* row = myy + tl * YROW + half * 16;
                u64 s0 = add2(row[0], row[4]);
                u64 s1 = add2(row[1], row[5]);
                u64 s2 = add2(row[2], row[6]);
                u64 s3 = add2(row[3], row[7]);
                s0 = add2(s0, add2(row[8],  row[12]));
                s1 = add2(s1, add2(row[9],  row[13]));
                s2 = add2(s2, add2(row[10], row[14]));
                s3 = add2(s3, add2(row[11], row[15]));
                u64 acc = add2(add2(s0, s1), add2(s2, s3));
                float2 v = unpack2(acc);
                v.x += __shfl_xor_sync(0xffffffffu, v.x, 16);
                v.y += __shfl_xor_sync(0xffffffffu, v.y, 16);
                if (half == 0)
                    outb[(s & 1) * YBUF_W + tl * YROW + wid] = pack2(v.x, v.y);
            }
        }

        // commit prefetched u tile into the other buffer
        if (loader && (s + 1) < NSUB) {
            ubuf[((s + 1) & 1) * UBUF_E + ltl * In + li] = pack2(p0, p1);
        }
        __syncthreads();

        // coalesced cooperative store of this sub-tile's outputs
        if (s >= WARMSUB) {
            int e    = tid & 511;          // t_local*32 + o
            int bsel = tid >> 9;
            int tl = e >> 5, o = e & 31;
            float2 v = unpack2(outb[(s & 1) * YBUF_W + tl * YROW + o]);
            int t = t0 + s * TS + tl;
            if (bsel) Y1[(size_t)t * On + o] = v.y;
            else      Y0[(size_t)t * On + o] = v.x;
        }
    }
}

extern "C" void kernel_launch(void* const* d_in, const int* in_sizes, int n_in,
                              void* d_out, int out_size)
{
    const float* u  = (const float*)d_in[0];   // u_in   (B,T,I) f32
    const float* bc = (const float*)d_in[1];   // b_coeff (O,I,3) f32
    const float* ac = (const float*)d_in[2];   // a_coeff (O,I,2) f32
    float* y = (float*)d_out;                  // (B,T,O) f32

    cudaFuncSetAttribute(mimo_iir_kernel,
                         cudaFuncAttributeMaxDynamicSharedMemorySize, SMEM_BYTES);
    dim3 grid(C, BP);                          // 16 x 8 = 128 blocks
    mimo_iir_kernel<<<grid, 1024, SMEM_BYTES>>>(u, bc, ac, y);
}

// round 2
// speedup vs baseline: 1.2359x; 1.2359x over previous
#include <cuda_runtime.h>

// Problem dims (fixed)
constexpr int Bn = 16, Tn = 4096, In = 32, On = 32;

// Chunked scan
constexpr int C  = 16;            // time chunks
constexpr int Lc = Tn / C;        // 256 outputs per chunk
constexpr int W  = 48;            // warm-up (max pole ~0.65 -> truncation ~1e-9)
constexpr int TS = 16;            // time sub-tile
constexpr int WARMSUB = W / TS;   // 3
constexpr int NSUB = (W + Lc) / TS; // 19
constexpr int UPB = 2;            // units (b,chunk) per block
constexpr int THREADS = UPB * 128;
constexpr int NBLOCK = (Bn * C) / UPB;   // 128

using u64   = unsigned long long;
using u64x2 = ulonglong2;

static __device__ __forceinline__ u64 pack2(float lo, float hi) {
    u64 r; asm("mov.b64 %0, {%1, %2};" : "=l"(r) : "f"(lo), "f"(hi)); return r;
}
static __device__ __forceinline__ float2 unpack2(u64 v) {
    float2 r; asm("mov.b64 {%0, %1}, %2;" : "=f"(r.x), "=f"(r.y) : "l"(v)); return r;
}
static __device__ __forceinline__ u64 fma2(u64 a, u64 b, u64 c) {
    u64 d; asm("fma.rn.f32x2 %0, %1, %2, %3;" : "=l"(d) : "l"(a), "l"(b), "l"(c)); return d;
}
static __device__ __forceinline__ u64 mul2(u64 a, u64 b) {
    u64 d; asm("mul.rn.f32x2 %0, %1, %2;" : "=l"(d) : "l"(a), "l"(b)); return d;
}
static __device__ __forceinline__ u64 add2(u64 a, u64 b) {
    u64 d; asm("add.rn.f32x2 %0, %1, %2;" : "=l"(d) : "l"(a), "l"(b)); return d;
}

// SMEM (u64 units):
//  pbuf: [UPB][2 buf][4 warps][TS=16 rows][32 o]  = 8192 u64 (64 KB)
//  ubuf: [UPB][2 buf][TS=16 rows][16 u64]          = 1024 u64 (8 KB)
constexpr int PBUF_U64 = UPB * 2 * 4 * 16 * 32;
constexpr int UBUF_U64 = UPB * 2 * 16 * 16;
constexpr int SMEM_BYTES = (PBUF_U64 + UBUF_U64) * 8;   // 73,728 B

__global__ void __launch_bounds__(THREADS, 1)
mimo_iir2(const float* __restrict__ u_in,
          const float* __restrict__ b_co,
          const float* __restrict__ a_co,
          float* __restrict__ y_out)
{
    extern __shared__ u64 sm[];
    u64*   pbuf = sm;
    u64*   ubuf = sm + PBUF_U64;
    float* smf  = (float*)sm;          // coeff staging overlays pbuf (synced)

    const int tid  = threadIdx.x;
    const int lane = tid & 31;         // o channel
    const int wid  = tid >> 5;
    const int unit = wid >> 2;         // unit within block
    const int wu   = wid & 3;          // i-octet index (i in [8*wu, 8*wu+8))
    const int ut   = tid & 127;        // thread id within unit

    const int gunit = blockIdx.x * UPB + unit;
    const int bb = gunit >> 4;         // batch
    const int cc = gunit & 15;         // chunk
    const int t0 = cc * Lc - W;        // first (warm-up) global step

    const u64* Ub = (const u64*)(u_in + (size_t)bb * Tn * In);  // 16 u64 per t-row
    float* Y = y_out + (size_t)bb * Tn * On;

    // ---- stage coefficients, padded (+j/96, +j/64) for conflict-free reads ----
    for (int j = tid; j < On * In * 3; j += THREADS) smf[j + j / 96] = b_co[j];
    const int AOFF = On * In * 3 + 32;   // 3104
    for (int j = tid; j < On * In * 2; j += THREADS) smf[AOFF + j + j / 64] = a_co[j];
    __syncthreads();

    u64 B0[4], B1[4], B2[4], A1[4], A2[4];
    #pragma unroll
    for (int p = 0; p < 4; ++p) {
        const int i0 = wu * 8 + 2 * p, i1 = i0 + 1;
        const int jb0 = (lane * In + i0) * 3, jb1 = (lane * In + i1) * 3;
        #define LDB(j) smf[(j) + (j) / 96]
        #define LDA(j) smf[AOFF + (j) + (j) / 64]
        B0[p] = pack2(LDB(jb0 + 0), LDB(jb1 + 0));
        B1[p] = pack2(LDB(jb0 + 1), LDB(jb1 + 1));
        B2[p] = pack2(LDB(jb0 + 2), LDB(jb1 + 2));
        const int ja0 = (lane * In + i0) * 2, ja1 = (lane * In + i1) * 2;
        A1[p] = pack2(-LDA(ja0 + 0), -LDA(ja1 + 0));
        A2[p] = pack2(-LDA(ja0 + 1), -LDA(ja1 + 1));
        #undef LDB
        #undef LDA
    }

    // ---- prologue: load u sub-tile 0 into ubuf[unit][0] ----
    {
        const int row = ut >> 3, part = ut & 7;     // 8 ull2 per 32-float row
        const int tg = t0 + row;
        u64x2 pre = make_ulonglong2(0ull, 0ull);
        if (tg >= 0) pre = ((const u64x2*)Ub)[tg * 8 + part];
        ((u64x2*)(ubuf + unit * 2 * 256))[row * 8 + part] = pre;
    }
    __syncthreads();   // coeffs read + ubuf[0] ready; pbuf overlay now reusable

    // rolling per-pair state (packed over adjacent i's)
    u64 uh1[4] = {0,0,0,0}, uh2[4] = {0,0,0,0};
    u64 ys1[4] = {0,0,0,0}, ys2[4] = {0,0,0,0};

    for (int sub = 0; sub < NSUB; ++sub) {
        // prefetch next u sub-tile (registers; LDG overlaps 16 steps of compute)
        u64x2 nxt = make_ulonglong2(0ull, 0ull);
        const int row = ut >> 3, part = ut & 7;
        if (sub + 1 < NSUB) {
            const int tg = t0 + (sub + 1) * TS + row;
            if (tg >= 0) nxt = ((const u64x2*)Ub)[tg * 8 + part];
        }

        const u64* ub = ubuf + (unit * 2 + (sub & 1)) * 256;
        u64* pw = pbuf + ((unit * 2 + (sub & 1)) * 4 + wu) * 512;
        const bool outp = (sub >= WARMSUB);

        #pragma unroll
        for (int k = 0; k < TS; ++k) {
            // broadcast reads: all lanes read the same 32B of u for this octet
            u64x2 qa = *(const u64x2*)(ub + k * 16 + 4 * wu);
            u64x2 qb = *(const u64x2*)(ub + k * 16 + 4 * wu + 2);
            u64 uc[4] = {qa.x, qa.y, qb.x, qb.y};
            u64 yv[4];
            #pragma unroll
            for (int p = 0; p < 4; ++p) {
                u64 x = fma2(B1[p], uh1[p], mul2(B2[p], uh2[p]));
                x = fma2(B0[p], uc[p], x);
                u64 y = fma2(A2[p], ys2[p], x);
                y = fma2(A1[p], ys1[p], y);
                uh2[p] = uh1[p]; uh1[p] = uc[p];
                ys2[p] = ys1[p]; ys1[p] = y;
                yv[p] = y;
            }
            if (outp) {
                // partial sum over this thread's 8 i's (still packed even/odd)
                pw[k * 32 + lane] = add2(add2(yv[0], yv[1]), add2(yv[2], yv[3]));
            }
        }

        // commit prefetched u tile
        if (sub + 1 < NSUB) {
            ((u64x2*)(ubuf + (unit * 2 + ((sub + 1) & 1)) * 256))[row * 8 + part] = nxt;
        }
        __syncthreads();

        // cross-warp reduce (4 partials) + store; warp wu handles rows wu*4..wu*4+3
        if (outp) {
            const u64* pr = pbuf + (unit * 2 + (sub & 1)) * 4 * 512;
            const int tb = t0 + sub * TS;
            #pragma unroll
            for (int r0 = 0; r0 < 4; ++r0) {
                const int r = wu * 4 + r0;
                u64 s01 = add2(pr[0 * 512 + r * 32 + lane], pr[1 * 512 + r * 32 + lane]);
                u64 s23 = add2(pr[2 * 512 + r * 32 + lane], pr[3 * 512 + r * 32 + lane]);
                float2 v = unpack2(add2(s01, s23));
                Y[(size_t)(tb + r) * On + lane] = v.x + v.y;
            }
        }
    }
}

extern "C" void kernel_launch(void* const* d_in, const int* in_sizes, int n_in,
                              void* d_out, int out_size)
{
    const float* u  = (const float*)d_in[0];   // (B,T,I) f32
    const float* bc = (const float*)d_in[1];   // (O,I,3) f32
    const float* ac = (const float*)d_in[2];   // (O,I,2) f32
    float* y = (float*)d_out;                  // (B,T,O) f32

    cudaFuncSetAttribute(mimo_iir2,
                         cudaFuncAttributeMaxDynamicSharedMemorySize, SMEM_BYTES);
    mimo_iir2<<<NBLOCK, THREADS, SMEM_BYTES>>>(u, bc, ac, y);
}